// round 8
// baseline (speedup 1.0000x reference)
#include <cuda_runtime.h>

#define L_SEQ 256
#define D_HEAD 64
#define MASK_VAL (-4294967295.0f)   // -2^32 + 1
#define ROW_F4 4096                  // 256*64/4 float4 per bhq slab of TMK/TMV
#define BH_F4  4096                  // 256*64/4 float4 per (b,h) slab of K/V

__device__ __forceinline__ void stcs_f(float* p, float v) {
    asm volatile("st.global.cs.f32 [%0], %1;" :: "l"(p), "f"(v) : "memory");
}

// esh_e[tid] (energies) -> esh_a[tid] (weights), optional AW row write.
// 3 internal barriers; trailing barrier makes esh_a visible.
__device__ __forceinline__ void softmax_row(
    const float* __restrict__ esh_e, float* __restrict__ esh_a,
    float* red_m, float* red_s, float* gred,
    float* __restrict__ AW, size_t awoff, int write_aw,
    int tid, int w, int lane)
{
    const float v = esh_e[tid];
    float wm = v;
    #pragma unroll
    for (int o = 16; o > 0; o >>= 1)
        wm = fmaxf(wm, __shfl_xor_sync(0xffffffffu, wm, o));
    float ws = __expf(v - wm);
    #pragma unroll
    for (int o = 16; o > 0; o >>= 1)
        ws += __shfl_xor_sync(0xffffffffu, ws, o);
    if (lane == 0) { red_m[w] = wm; red_s[w] = ws; }
    __syncthreads();
    if (w == 0) {
        float mi = (lane < 8) ? red_m[lane] : MASK_VAL;
        float si = (lane < 8) ? red_s[lane] : 0.0f;
        float gm = mi;
        #pragma unroll
        for (int o = 4; o > 0; o >>= 1)
            gm = fmaxf(gm, __shfl_xor_sync(0xffffffffu, gm, o));
        float z = si * __expf(mi - gm);
        #pragma unroll
        for (int o = 4; o > 0; o >>= 1)
            z += __shfl_xor_sync(0xffffffffu, z, o);
        if (lane == 0) { gred[0] = gm; gred[1] = 1.0f / z; }
    }
    __syncthreads();
    const float a = __expf(v - gred[0]) * gred[1];
    esh_a[tid] = a;
    if (write_aw) stcs_f(AW + awoff + tid, a);
    __syncthreads();
}

// Persistent CTAs, 256 threads, 5 CTAs/SM. Pipeline: B(row) fused with A(row+stride).
__global__ __launch_bounds__(256, 5)
void tasdp_kernel(const float* __restrict__ Q,
                  const float* __restrict__ Km,
                  const float* __restrict__ V,
                  const float* __restrict__ TMK,
                  const float* __restrict__ TMV,
                  const float* __restrict__ AM,
                  const unsigned char* __restrict__ PM,
                  float* __restrict__ O,
                  float* __restrict__ AW,
                  int H, int write_aw, int total)
{
    __shared__ float  esh_a[L_SEQ];    // attn weights of current row
    __shared__ float  esh_e[L_SEQ];    // energies of next row
    __shared__ float  red_m[8], red_s[8], gred[2];
    __shared__ float4 acc_sh[16][16];

    const int tid  = threadIdx.x;
    const int w    = tid >> 5;
    const int lane = tid & 31;
    const int f4   = tid & 15;         // float4 chunk within d
    const int hw   = tid >> 4;         // half-warp id 0..15 (== k row offset)

    int row = blockIdx.x;
    const int stride = gridDim.x;
    if (row >= total) return;

    // ---------- prologue: Phase A for first row ----------
    {
        const int q = row & (L_SEQ - 1), bh = row >> 8, b = bh / H;
        const float4 q4 = __ldg((const float4*)(Q + (size_t)row * D_HEAD) + f4);
        const float4* tkp = (const float4*)TMK + (size_t)row * ROW_F4 + hw * 16 + f4;
        const float4* kkp = (const float4*)Km  + (size_t)bh  * BH_F4  + hw * 16 + f4;
        const float*         amrow = AM + q * L_SEQ;
        const unsigned char* pmrow = PM + b * L_SEQ;
        #pragma unroll 4
        for (int it = 0; it < 16; ++it) {
            float4 tk = __ldcs(tkp); float4 kx = __ldg(kkp);
            tkp += 256; kkp += 256;
            float s = (tk.x + kx.x) * q4.x + (tk.y + kx.y) * q4.y
                    + (tk.z + kx.z) * q4.z + (tk.w + kx.w) * q4.w;
            s += __shfl_xor_sync(0xffffffffu, s, 1);
            s += __shfl_xor_sync(0xffffffffu, s, 2);
            s += __shfl_xor_sync(0xffffffffu, s, 4);
            s += __shfl_xor_sync(0xffffffffu, s, 8);
            if (f4 == 0) {
                const int k = it * 16 + hw;
                float e = s * 0.125f + amrow[k];
                if (pmrow[k]) e = MASK_VAL;
                esh_e[k] = e;
            }
        }
        __syncthreads();
    }

    // ---------- steady state ----------
    for (;;) {
        // softmax for 'row' (energies in esh_e) -> weights in esh_a
        softmax_row(esh_e, esh_a, red_m, red_s, gred,
                    AW, (size_t)row * L_SEQ, write_aw, tid, w, lane);

        const int nrow = row + stride;
        const int bh_c = row >> 8;
        float4 acc = make_float4(0.f, 0.f, 0.f, 0.f);

        if (nrow < total) {
            // fused: B(row) + A(nrow)
            const int qn = nrow & (L_SEQ - 1), bhn = nrow >> 8, bn = bhn / H;
            const float4 q4 = __ldg((const float4*)(Q + (size_t)nrow * D_HEAD) + f4);
            const float4* tvp = (const float4*)TMV + (size_t)row  * ROW_F4 + hw * 16 + f4;
            const float4* vvp = (const float4*)V   + (size_t)bh_c * BH_F4  + hw * 16 + f4;
            const float4* tkp = (const float4*)TMK + (size_t)nrow * ROW_F4 + hw * 16 + f4;
            const float4* kkp = (const float4*)Km  + (size_t)bhn  * BH_F4  + hw * 16 + f4;
            const float*         amrow = AM + qn * L_SEQ;
            const unsigned char* pmrow = PM + bn * L_SEQ;

            #pragma unroll 2
            for (int it = 0; it < 16; ++it) {
                float4 tv = __ldcs(tvp); float4 vx = __ldg(vvp);
                float4 tk = __ldcs(tkp); float4 kx = __ldg(kkp);
                tvp += 256; vvp += 256; tkp += 256; kkp += 256;

                const int k = it * 16 + hw;
                const float ak = esh_a[k];
                acc.x += ak * (tv.x + vx.x);
                acc.y += ak * (tv.y + vx.y);
                acc.z += ak * (tv.z + vx.z);
                acc.w += ak * (tv.w + vx.w);

                float s = (tk.x + kx.x) * q4.x + (tk.y + kx.y) * q4.y
                        + (tk.z + kx.z) * q4.z + (tk.w + kx.w) * q4.w;
                s += __shfl_xor_sync(0xffffffffu, s, 1);
                s += __shfl_xor_sync(0xffffffffu, s, 2);
                s += __shfl_xor_sync(0xffffffffu, s, 4);
                s += __shfl_xor_sync(0xffffffffu, s, 8);
                if (f4 == 0) {
                    float e = s * 0.125f + amrow[k];
                    if (pmrow[k]) e = MASK_VAL;
                    esh_e[k] = e;
                }
            }
            acc_sh[hw][f4] = acc;
            __syncthreads();

            if (tid < 16) {
                float4 r = acc_sh[0][tid];
                #pragma unroll
                for (int g = 1; g < 16; ++g) {
                    float4 p = acc_sh[g][tid];
                    r.x += p.x; r.y += p.y; r.z += p.z; r.w += p.w;
                }
                ((float4*)(O + (size_t)row * D_HEAD))[tid] = r;
            }
            row = nrow;        // esh_e now holds nrow's energies; loop to softmax
        } else {
            // epilogue: plain B(row)
            const float4* tvp = (const float4*)TMV + (size_t)row  * ROW_F4 + hw * 16 + f4;
            const float4* vvp = (const float4*)V   + (size_t)bh_c * BH_F4  + hw * 16 + f4;
            #pragma unroll 4
            for (int it = 0; it < 16; ++it) {
                float4 tv = __ldcs(tvp); float4 vx = __ldg(vvp);
                tvp += 256; vvp += 256;
                const float ak = esh_a[it * 16 + hw];
                acc.x += ak * (tv.x + vx.x);
                acc.y += ak * (tv.y + vx.y);
                acc.z += ak * (tv.z + vx.z);
                acc.w += ak * (tv.w + vx.w);
            }
            acc_sh[hw][f4] = acc;
            __syncthreads();
            if (tid < 16) {
                float4 r = acc_sh[0][tid];
                #pragma unroll
                for (int g = 1; g < 16; ++g) {
                    float4 p = acc_sh[g][tid];
                    r.x += p.x; r.y += p.y; r.z += p.z; r.w += p.w;
                }
                ((float4*)(O + (size_t)row * D_HEAD))[tid] = r;
            }
            break;
        }
    }
}

extern "C" void kernel_launch(void* const* d_in, const int* in_sizes, int n_in,
                              void* d_out, int out_size)
{
    const float*         Q   = (const float*)d_in[0];
    const float*         Km  = (const float*)d_in[1];
    const float*         V   = (const float*)d_in[2];
    const float*         TMK = (const float*)d_in[3];
    const float*         TMV = (const float*)d_in[4];
    const float*         AM  = (const float*)d_in[5];
    const unsigned char* PM  = (const unsigned char*)d_in[6];

    const int L = 256, D = 64;
    const int b = in_sizes[6] / L;                 // padding_mask is [b, L]
    const int h = in_sizes[0] / (b * L * D);       // Q is [b, h, L, D]

    const int nO  = b * h * L * D;
    const int nAW = b * h * L * L;
    const int total = b * h * L;

    float* O  = (float*)d_out;
    float* AW = O + nO;
    const int write_aw = (out_size >= nO + nAW) ? 1 : 0;

    int sms = 148;
    cudaDeviceGetAttribute(&sms, cudaDevAttrMultiProcessorCount, 0);
    int grid = sms * 5;
    if (grid > total) grid = total;

    tasdp_kernel<<<grid, 256>>>(Q, Km, V, TMK, TMV, AM, PM, O, AW, h, write_aw, total);
}